// round 10
// baseline (speedup 1.0000x reference)
#include <cuda_runtime.h>
#include <cuda_bf16.h>

// Persistent one-wave kernel: grid = 148 SMs x 8 CTAs, grid-stride loop over
// float4 groups. Every thread computes the 3x4 SE(3) matrix once from the
// scalar inputs (uniform broadcast loads), then streams points with 128-bit
// evict-first loads/stores (__ldcs/__stcs — validated in earlier rounds).
__global__ void __launch_bounds__(256)
transform_fused_kernel(const float4* __restrict__ x, float4* __restrict__ out,
                       const float* __restrict__ w, const float* __restrict__ v,
                       const float* __restrict__ theta, const int* __restrict__ cam,
                       int n4) {
    // ---- Matrix from scalars (computed once per thread) ----
    int ci = cam[0];
    float w0 = w[ci * 3 + 0], w1 = w[ci * 3 + 1], w2 = w[ci * 3 + 2];
    float v0 = v[ci * 3 + 0], v1 = v[ci * 3 + 1], v2 = v[ci * 3 + 2];
    float th = theta[ci];

    float s = sinf(th), c = cosf(th);
    float A = 1.0f - c;
    float B = th - s;

    // K = skew(w); K2 = K*K (zero-diagonal terms folded out)
    float K01 = -w2, K02 = w1;
    float K10 = w2,  K12 = -w0;
    float K20 = -w1, K21 = w0;

    float K2_00 = K01*K10 + K02*K20;
    float K2_01 = K02*K21;
    float K2_02 = K01*K12;
    float K2_10 = K12*K20;
    float K2_11 = K10*K01 + K12*K21;
    float K2_12 = K10*K02;
    float K2_20 = K21*K10;
    float K2_21 = K20*K01;
    float K2_22 = K20*K02 + K21*K12;

    // R = I + s*K + A*K2
    float m00 = 1.0f + A*K2_00;
    float m01 =        s*K01 + A*K2_01;
    float m02 =        s*K02 + A*K2_02;
    float m10 =        s*K10 + A*K2_10;
    float m11 = 1.0f + A*K2_11;
    float m12 =        s*K12 + A*K2_12;
    float m20 =        s*K20 + A*K2_20;
    float m21 =        s*K21 + A*K2_21;
    float m22 = 1.0f + A*K2_22;

    // V = I*th + A*K + B*K2 ; t = V @ v
    float V00 = th + B*K2_00;
    float V01 =      A*K01 + B*K2_01;
    float V02 =      A*K02 + B*K2_02;
    float V10 =      A*K10 + B*K2_10;
    float V11 = th + B*K2_11;
    float V12 =      A*K12 + B*K2_12;
    float V20 =      A*K20 + B*K2_20;
    float V21 =      A*K21 + B*K2_21;
    float V22 = th + B*K2_22;

    float m03 = V00*v0 + V01*v1 + V02*v2;
    float m13 = V10*v0 + V11*v1 + V12*v2;
    float m23 = V20*v0 + V21*v1 + V22*v2;

    // ---- Grid-stride streaming loop over float4 groups ----
    int stride = gridDim.x * blockDim.x;
    for (int i = blockIdx.x * blockDim.x + threadIdx.x; i < n4; i += stride) {
        float4 x0 = __ldcs(x + i);
        float4 x1 = __ldcs(x + i + n4);
        float4 x2 = __ldcs(x + i + 2 * n4);
        float4 x3 = __ldcs(x + i + 3 * n4);

        float4 o0, o1, o2;
        o0.x = m00*x0.x + m01*x1.x + m02*x2.x + m03*x3.x;
        o0.y = m00*x0.y + m01*x1.y + m02*x2.y + m03*x3.y;
        o0.z = m00*x0.z + m01*x1.z + m02*x2.z + m03*x3.z;
        o0.w = m00*x0.w + m01*x1.w + m02*x2.w + m03*x3.w;

        o1.x = m10*x0.x + m11*x1.x + m12*x2.x + m13*x3.x;
        o1.y = m10*x0.y + m11*x1.y + m12*x2.y + m13*x3.y;
        o1.z = m10*x0.z + m11*x1.z + m12*x2.z + m13*x3.z;
        o1.w = m10*x0.w + m11*x1.w + m12*x2.w + m13*x3.w;

        o2.x = m20*x0.x + m21*x1.x + m22*x2.x + m23*x3.x;
        o2.y = m20*x0.y + m21*x1.y + m22*x2.y + m23*x3.y;
        o2.z = m20*x0.z + m21*x1.z + m22*x2.z + m23*x3.z;
        o2.w = m20*x0.w + m21*x1.w + m22*x2.w + m23*x3.w;

        __stcs(out + i,          o0);
        __stcs(out + i + n4,     o1);
        __stcs(out + i + 2 * n4, o2);
        __stcs(out + i + 3 * n4, x3);   // bottom row [0,0,0,1] @ x == x[3]
    }
}

extern "C" void kernel_launch(void* const* d_in, const int* in_sizes, int n_in,
                              void* d_out, int out_size) {
    const float* x     = (const float*)d_in[0];   // [4, N]
    const float* w     = (const float*)d_in[1];   // [16, 3]
    const float* v     = (const float*)d_in[2];   // [16, 3]
    const float* theta = (const float*)d_in[3];   // [16, 1]
    const int*   cam   = (const int*)d_in[4];     // scalar

    int N  = in_sizes[0] / 4;   // points per row (8388608)
    int n4 = N / 4;             // float4 groups per row

    // One-wave persistent grid: 148 SMs x 8 CTAs x 256 threads.
    int threads = 256;
    int blocks  = 148 * 8;
    transform_fused_kernel<<<blocks, threads>>>(
        (const float4*)x, (float4*)d_out, w, v, theta, cam, n4);
}

// round 13
// speedup vs baseline: 1.0894x; 1.0894x over previous
#include <cuda_runtime.h>
#include <cuda_bf16.h>

// FINAL: fused single-kernel SE(3) point transform.
// - Every thread computes the 3x4 matrix from the scalar inputs (uniform
//   broadcast loads, ~50 FLOPs — free under the streaming loads).
// - One float4 group per row per thread, dense CTA mapping (best measured
//   DRAM locality: 38.2us kernel, 69.8% DRAM of 8TB/s).
// - __ldcs/__stcs evict-first policy on the 256MB once-touched stream.
// Measured ledger: plain (38.8), MLP8 (38.5), .cs (38.2, best), v8 256-bit
// (38.3), persistent grid (40.8) — ~5.7TB/s is the mixed read/write DRAM
// ceiling for this pattern.
__global__ void __launch_bounds__(256)
transform_fused_kernel(const float4* __restrict__ x, float4* __restrict__ out,
                       const float* __restrict__ w, const float* __restrict__ v,
                       const float* __restrict__ theta, const int* __restrict__ cam,
                       int n4) {
    int i = blockIdx.x * blockDim.x + threadIdx.x;
    if (i >= n4) return;

    // ---- Issue all 4 independent streaming loads first (evict-first) ----
    float4 x0 = __ldcs(x + i);
    float4 x1 = __ldcs(x + i + n4);
    float4 x2 = __ldcs(x + i + 2 * n4);
    float4 x3 = __ldcs(x + i + 3 * n4);

    // ---- Compute the matrix while loads are in flight ----
    int ci = cam[0];
    float w0 = w[ci * 3 + 0], w1 = w[ci * 3 + 1], w2 = w[ci * 3 + 2];
    float v0 = v[ci * 3 + 0], v1 = v[ci * 3 + 1], v2 = v[ci * 3 + 2];
    float th = theta[ci];

    float s = sinf(th), c = cosf(th);
    float A = 1.0f - c;
    float B = th - s;

    // K = skew(w); K2 = K*K (zero-diagonal terms folded out)
    float K01 = -w2, K02 = w1;
    float K10 = w2,  K12 = -w0;
    float K20 = -w1, K21 = w0;

    float K2_00 = K01*K10 + K02*K20;
    float K2_01 = K02*K21;
    float K2_02 = K01*K12;
    float K2_10 = K12*K20;
    float K2_11 = K10*K01 + K12*K21;
    float K2_12 = K10*K02;
    float K2_20 = K21*K10;
    float K2_21 = K20*K01;
    float K2_22 = K20*K02 + K21*K12;

    // R = I + s*K + A*K2
    float m00 = 1.0f + A*K2_00;
    float m01 =        s*K01 + A*K2_01;
    float m02 =        s*K02 + A*K2_02;
    float m10 =        s*K10 + A*K2_10;
    float m11 = 1.0f + A*K2_11;
    float m12 =        s*K12 + A*K2_12;
    float m20 =        s*K20 + A*K2_20;
    float m21 =        s*K21 + A*K2_21;
    float m22 = 1.0f + A*K2_22;

    // V = I*th + A*K + B*K2 ; t = V @ v
    float V00 = th + B*K2_00;
    float V01 =      A*K01 + B*K2_01;
    float V02 =      A*K02 + B*K2_02;
    float V10 =      A*K10 + B*K2_10;
    float V11 = th + B*K2_11;
    float V12 =      A*K12 + B*K2_12;
    float V20 =      A*K20 + B*K2_20;
    float V21 =      A*K21 + B*K2_21;
    float V22 = th + B*K2_22;

    float m03 = V00*v0 + V01*v1 + V02*v2;
    float m13 = V10*v0 + V11*v1 + V12*v2;
    float m23 = V20*v0 + V21*v1 + V22*v2;

    // ---- Transform ----
    float4 o0, o1, o2;
    o0.x = m00*x0.x + m01*x1.x + m02*x2.x + m03*x3.x;
    o0.y = m00*x0.y + m01*x1.y + m02*x2.y + m03*x3.y;
    o0.z = m00*x0.z + m01*x1.z + m02*x2.z + m03*x3.z;
    o0.w = m00*x0.w + m01*x1.w + m02*x2.w + m03*x3.w;

    o1.x = m10*x0.x + m11*x1.x + m12*x2.x + m13*x3.x;
    o1.y = m10*x0.y + m11*x1.y + m12*x2.y + m13*x3.y;
    o1.z = m10*x0.z + m11*x1.z + m12*x2.z + m13*x3.z;
    o1.w = m10*x0.w + m11*x1.w + m12*x2.w + m13*x3.w;

    o2.x = m20*x0.x + m21*x1.x + m22*x2.x + m23*x3.x;
    o2.y = m20*x0.y + m21*x1.y + m22*x2.y + m23*x3.y;
    o2.z = m20*x0.z + m21*x1.z + m22*x2.z + m23*x3.z;
    o2.w = m20*x0.w + m21*x1.w + m22*x2.w + m23*x3.w;

    // ---- Streaming stores ----
    __stcs(out + i,          o0);
    __stcs(out + i + n4,     o1);
    __stcs(out + i + 2 * n4, o2);
    __stcs(out + i + 3 * n4, x3);   // bottom row [0,0,0,1] @ x == x[3]
}

extern "C" void kernel_launch(void* const* d_in, const int* in_sizes, int n_in,
                              void* d_out, int out_size) {
    const float* x     = (const float*)d_in[0];   // [4, N]
    const float* w     = (const float*)d_in[1];   // [16, 3]
    const float* v     = (const float*)d_in[2];   // [16, 3]
    const float* theta = (const float*)d_in[3];   // [16, 1]
    const int*   cam   = (const int*)d_in[4];     // scalar

    int N  = in_sizes[0] / 4;   // points per row
    int n4 = N / 4;             // float4 groups per row

    int threads = 256;
    int blocks  = (n4 + threads - 1) / threads;
    transform_fused_kernel<<<blocks, threads>>>(
        (const float4*)x, (float4*)d_out, w, v, theta, cam, n4);
}